// round 5
// baseline (speedup 1.0000x reference)
#include <cuda_runtime.h>

#define NB 32
#define NT 196
#define PD 768
#define DM 512
#define NC 1000
#define MTOT (NB*NT)

__device__ float g_X [(size_t)MTOT*PD];
__device__ float g_Q [(size_t)MTOT*DM];
__device__ float g_V [(size_t)MTOT*DM];
__device__ float g_M [(size_t)NB*NT*NT];
__device__ float g_Xa[(size_t)NB*NT*NT];
__device__ float g_Xb[(size_t)NB*NT*NT];
__device__ float g_T [(size_t)NB*NT*NT];
__device__ float g_P [(size_t)NB*NT*NT];
__device__ float g_Cf[(size_t)NB*NT*NT];
__device__ float g_O [(size_t)MTOT*DM];
__device__ float g_pool[NB*DM];

typedef unsigned long long ull;

__device__ __forceinline__ float clipf(float x){ return fminf(fmaxf(x, 0.f), 1.f); }

__device__ __forceinline__ ull pk2(float x, float y){
    ull r; asm("mov.b64 %0, {%1, %2};" : "=l"(r) : "f"(x), "f"(y)); return r;
}
__device__ __forceinline__ void upk2(ull v, float& x, float& y){
    asm("mov.b64 {%0, %1}, %2;" : "=f"(x), "=f"(y) : "l"(v));
}
__device__ __forceinline__ ull fma2(ull a, ull b, ull c){
    ull d; asm("fma.rn.f32x2 %0, %1, %2, %3;" : "=l"(d) : "l"(a), "l"(b), "l"(c)); return d;
}

__device__ __forceinline__ float4 ld4g(const float* p, int rem){
    if (rem >= 4) return *(const float4*)p;
    float4 v = make_float4(0.f,0.f,0.f,0.f);
    if (rem > 0) v.x = p[0];
    if (rem > 1) v.y = p[1];
    if (rem > 2) v.z = p[2];
    return v;
}

// ---------------- patchify + LN(768) + pos ----------------
__global__ void k_patchify(const float* __restrict__ img, const float* __restrict__ g,
                           const float* __restrict__ bb, const float* __restrict__ pos){
    int bn = blockIdx.x, b = bn / NT, n = bn % NT;
    int hh = n / 14, ww = n % 14;
    int tid = threadIdx.x, ph = tid >> 4, pw = tid & 15;
    const float* ib = img + (size_t)b*3*224*224 + (size_t)(hh*16+ph)*224 + (ww*16+pw);
    float v0 = ib[0], v1 = ib[224*224], v2 = ib[2*224*224];
    __shared__ float red[256]; __shared__ float smu, srs;
    red[tid] = v0+v1+v2; __syncthreads();
    for (int o=128;o;o>>=1){ if (tid<o) red[tid]+=red[tid+o]; __syncthreads(); }
    if (!tid) smu = red[0]/768.f;
    __syncthreads();
    float mu = smu, d0=v0-mu, d1=v1-mu, d2=v2-mu;
    red[tid] = d0*d0+d1*d1+d2*d2; __syncthreads();
    for (int o=128;o;o>>=1){ if (tid<o) red[tid]+=red[tid+o]; __syncthreads(); }
    if (!tid) srs = rsqrtf(red[0]/768.f + 1e-5f);
    __syncthreads();
    float rs = srs;
    float* xo = g_X + (size_t)bn*PD;
    const float* pp = pos + (size_t)n*PD;
    int q = tid;     xo[q] = d0*rs*g[q] + bb[q] + pp[q];
    q = 256+tid;     xo[q] = d1*rs*g[q] + bb[q] + pp[q];
    q = 512+tid;     xo[q] = d2*rs*g[q] + bb[q] + pp[q];
}

// ---------------- fused projections (f32x2 inner) ----------------
__global__ void __launch_bounds__(256,2) k_proj(const float* __restrict__ X,
                       const float* __restrict__ Wq, const float* __restrict__ bq,
                       const float* __restrict__ Wv, const float* __restrict__ bv,
                       float* __restrict__ Qo, float* __restrict__ Vo){
    __shared__ float As[2][16][128];
    __shared__ float Bs[2][16][128];
    const float* B   = blockIdx.z ? Wv : Wq;
    const float* bia = blockIdx.z ? bv : bq;
    float* C         = blockIdx.z ? Vo : Qo;
    const int Nv = DM, Kv = PD;
    int tid = threadIdx.x;
    int m0 = blockIdx.y<<7, n0 = blockIdx.x<<7;
    int ty = tid>>4, tx = tid&15;
    int aRow = tid>>1, aK = (tid&1)<<3;
    int bK = tid>>4, bN = (tid&15)<<3;
    const float* Ap = X + (size_t)(m0+aRow)*Kv + aK;
    const float* Bp = B + (size_t)bK*Nv + n0 + bN;
    float4 pa0 = *(const float4*)(Ap);
    float4 pa1 = *(const float4*)(Ap+4);
    float4 pb0 = *(const float4*)(Bp);
    float4 pb1 = *(const float4*)(Bp+4);
    As[0][aK+0][aRow]=pa0.x; As[0][aK+1][aRow]=pa0.y; As[0][aK+2][aRow]=pa0.z; As[0][aK+3][aRow]=pa0.w;
    As[0][aK+4][aRow]=pa1.x; As[0][aK+5][aRow]=pa1.y; As[0][aK+6][aRow]=pa1.z; As[0][aK+7][aRow]=pa1.w;
    *(float4*)&Bs[0][bK][bN] = pb0; *(float4*)&Bs[0][bK][bN+4] = pb1;
    __syncthreads();
    ull accp[8][4] = {};
    const int NP = Kv>>4;
    int buf = 0;
    for (int p=0;p<NP;p++){
        bool more = (p+1)<NP;
        if (more){
            int k0 = (p+1)<<4;
            pa0 = *(const float4*)(Ap + k0);
            pa1 = *(const float4*)(Ap + k0 + 4);
            pb0 = *(const float4*)(Bp + (size_t)k0*Nv);
            pb1 = *(const float4*)(Bp + (size_t)k0*Nv + 4);
        }
#pragma unroll
        for (int kk=0;kk<16;kk++){
            float4 a0=*(const float4*)&As[buf][kk][ty<<3];
            float4 a1=*(const float4*)&As[buf][kk][(ty<<3)+4];
            const ull* bp = (const ull*)&Bs[buf][kk][tx<<3];
            ull b0=bp[0], b1=bp[1], b2=bp[2], b3=bp[3];
            float av[8]={a0.x,a0.y,a0.z,a0.w,a1.x,a1.y,a1.z,a1.w};
#pragma unroll
            for (int r=0;r<8;r++){
                ull ad = pk2(av[r], av[r]);
                accp[r][0]=fma2(ad,b0,accp[r][0]); accp[r][1]=fma2(ad,b1,accp[r][1]);
                accp[r][2]=fma2(ad,b2,accp[r][2]); accp[r][3]=fma2(ad,b3,accp[r][3]);
            }
        }
        if (more){
            int nb = buf^1;
            As[nb][aK+0][aRow]=pa0.x; As[nb][aK+1][aRow]=pa0.y; As[nb][aK+2][aRow]=pa0.z; As[nb][aK+3][aRow]=pa0.w;
            As[nb][aK+4][aRow]=pa1.x; As[nb][aK+5][aRow]=pa1.y; As[nb][aK+6][aRow]=pa1.z; As[nb][aK+7][aRow]=pa1.w;
            *(float4*)&Bs[nb][bK][bN] = pb0; *(float4*)&Bs[nb][bK][bN+4] = pb1;
            __syncthreads();
            buf = nb;
        }
    }
    float4 bi0 = *(const float4*)(bia + n0 + (tx<<3));
    float4 bi1 = *(const float4*)(bia + n0 + (tx<<3) + 4);
#pragma unroll
    for (int r=0;r<8;r++){
        int gm = m0 + (ty<<3) + r;
        float c0,c1,c2,c3,c4,c5,c6,c7;
        upk2(accp[r][0],c0,c1); upk2(accp[r][1],c2,c3);
        upk2(accp[r][2],c4,c5); upk2(accp[r][3],c6,c7);
        float4 o0 = make_float4(c0+bi0.x, c1+bi0.y, c2+bi0.z, c3+bi0.w);
        float4 o1 = make_float4(c4+bi1.x, c5+bi1.y, c6+bi1.z, c7+bi1.w);
        *(float4*)(C + (size_t)gm*Nv + n0 + (tx<<3)) = o0;
        *(float4*)(C + (size_t)gm*Nv + n0 + (tx<<3) + 4) = o1;
    }
}

// ---------------- in-place rowwise LN(512), then *scale ----------------
__global__ void k_ln512(float* __restrict__ y0, const float* __restrict__ g,
                        const float* __restrict__ bb, float scale){
    float* y = y0 + (size_t)blockIdx.x*DM;
    int tid = threadIdx.x;
    float v0 = y[tid], v1 = y[tid+256];
    __shared__ float red[256]; __shared__ float smu, srs;
    red[tid] = v0+v1; __syncthreads();
    for (int o=128;o;o>>=1){ if (tid<o) red[tid]+=red[tid+o]; __syncthreads(); }
    if (!tid) smu = red[0]/512.f;
    __syncthreads();
    float mu = smu, d0=v0-mu, d1=v1-mu;
    red[tid] = d0*d0+d1*d1; __syncthreads();
    for (int o=128;o;o>>=1){ if (tid<o) red[tid]+=red[tid+o]; __syncthreads(); }
    if (!tid) srs = rsqrtf(red[0]/512.f + 1e-5f);
    __syncthreads();
    float rs = srs;
    y[tid]     = (d0*rs*g[tid]     + bb[tid])     * scale;
    y[tid+256] = (d1*rs*g[tid+256] + bb[tid+256]) * scale;
}

// ---------------- batched GEMM 128x128 (f32x2 inner) ----------------
// C = alpha*A@op(B) + c0 + diag*I
__global__ void __launch_bounds__(256,2) k_bgemm(const float* __restrict__ A0, const float* __restrict__ B0,
                        float* __restrict__ C0, int M, int N, int K, int transB,
                        float alpha, float c0, float diag){
    __shared__ float As[2][16][128];
    __shared__ float Bs[2][16][128];
    const float* A = A0 + (size_t)blockIdx.z*M*K;
    const float* B = B0 + (size_t)blockIdx.z*((size_t)N*K);
    float* C = C0 + (size_t)blockIdx.z*M*N;
    int tid = threadIdx.x;
    int m0 = blockIdx.y<<7, n0 = blockIdx.x<<7;
    int ty = tid>>4, tx = tid&15;
    int aRow = tid>>1, aK = (tid&1)<<3;
    bool aok = (m0+aRow) < M;
    int bRT = tid>>1, bKT = (tid&1)<<3;
    bool bokT = (n0+bRT) < N;
    int bK = tid>>4, bN = (tid&15)<<3;
    const int NP = (K+15)>>4;
    float4 pa0,pa1,pb0,pb1;
    {
        const float* Ap = A + (size_t)(m0+aRow)*K + aK;
        int remA = aok ? (K - aK) : 0;
        pa0 = ld4g(Ap, remA); pa1 = ld4g(Ap+4, remA-4);
        if (transB){
            const float* Bp = B + (size_t)(n0+bRT)*K + bKT;
            int remB = bokT ? (K - bKT) : 0;
            pb0 = ld4g(Bp, remB); pb1 = ld4g(Bp+4, remB-4);
        } else {
            const float* Bp = B + (size_t)bK*N + n0 + bN;
            int remB = (bK < K) ? (N-(n0+bN)) : 0;
            pb0 = ld4g(Bp, remB); pb1 = ld4g(Bp+4, remB-4);
        }
    }
    As[0][aK+0][aRow]=pa0.x; As[0][aK+1][aRow]=pa0.y; As[0][aK+2][aRow]=pa0.z; As[0][aK+3][aRow]=pa0.w;
    As[0][aK+4][aRow]=pa1.x; As[0][aK+5][aRow]=pa1.y; As[0][aK+6][aRow]=pa1.z; As[0][aK+7][aRow]=pa1.w;
    if (transB){
        Bs[0][bKT+0][bRT]=pb0.x; Bs[0][bKT+1][bRT]=pb0.y; Bs[0][bKT+2][bRT]=pb0.z; Bs[0][bKT+3][bRT]=pb0.w;
        Bs[0][bKT+4][bRT]=pb1.x; Bs[0][bKT+5][bRT]=pb1.y; Bs[0][bKT+6][bRT]=pb1.z; Bs[0][bKT+7][bRT]=pb1.w;
    } else {
        *(float4*)&Bs[0][bK][bN] = pb0; *(float4*)&Bs[0][bK][bN+4] = pb1;
    }
    __syncthreads();
    ull accp[8][4] = {};
    int buf = 0;
    for (int p=0;p<NP;p++){
        bool more = (p+1)<NP;
        if (more){
            int k0 = (p+1)<<4;
            const float* Ap = A + (size_t)(m0+aRow)*K + k0 + aK;
            int remA = aok ? (K - (k0+aK)) : 0;
            pa0 = ld4g(Ap, remA); pa1 = ld4g(Ap+4, remA-4);
            if (transB){
                const float* Bp = B + (size_t)(n0+bRT)*K + k0 + bKT;
                int remB = bokT ? (K - (k0+bKT)) : 0;
                pb0 = ld4g(Bp, remB); pb1 = ld4g(Bp+4, remB-4);
            } else {
                const float* Bp = B + (size_t)(k0+bK)*N + n0 + bN;
                int remB = ((k0+bK) < K) ? (N-(n0+bN)) : 0;
                pb0 = ld4g(Bp, remB); pb1 = ld4g(Bp+4, remB-4);
            }
        }
#pragma unroll
        for (int kk=0;kk<16;kk++){
            float4 a0=*(const float4*)&As[buf][kk][ty<<3];
            float4 a1=*(const float4*)&As[buf][kk][(ty<<3)+4];
            const ull* bp = (const ull*)&Bs[buf][kk][tx<<3];
            ull b0=bp[0], b1=bp[1], b2=bp[2], b3=bp[3];
            float av[8]={a0.x,a0.y,a0.z,a0.w,a1.x,a1.y,a1.z,a1.w};
#pragma unroll
            for (int r=0;r<8;r++){
                ull ad = pk2(av[r], av[r]);
                accp[r][0]=fma2(ad,b0,accp[r][0]); accp[r][1]=fma2(ad,b1,accp[r][1]);
                accp[r][2]=fma2(ad,b2,accp[r][2]); accp[r][3]=fma2(ad,b3,accp[r][3]);
            }
        }
        if (more){
            int nb = buf^1;
            As[nb][aK+0][aRow]=pa0.x; As[nb][aK+1][aRow]=pa0.y; As[nb][aK+2][aRow]=pa0.z; As[nb][aK+3][aRow]=pa0.w;
            As[nb][aK+4][aRow]=pa1.x; As[nb][aK+5][aRow]=pa1.y; As[nb][aK+6][aRow]=pa1.z; As[nb][aK+7][aRow]=pa1.w;
            if (transB){
                Bs[nb][bKT+0][bRT]=pb0.x; Bs[nb][bKT+1][bRT]=pb0.y; Bs[nb][bKT+2][bRT]=pb0.z; Bs[nb][bKT+3][bRT]=pb0.w;
                Bs[nb][bKT+4][bRT]=pb1.x; Bs[nb][bKT+5][bRT]=pb1.y; Bs[nb][bKT+6][bRT]=pb1.z; Bs[nb][bKT+7][bRT]=pb1.w;
            } else {
                *(float4*)&Bs[nb][bK][bN] = pb0; *(float4*)&Bs[nb][bK][bN+4] = pb1;
            }
            __syncthreads();
            buf = nb;
        }
    }
#pragma unroll
    for (int r=0;r<8;r++){
        int gm = m0 + (ty<<3) + r;
        if (gm >= M) continue;
        float cv[8];
        upk2(accp[r][0],cv[0],cv[1]); upk2(accp[r][1],cv[2],cv[3]);
        upk2(accp[r][2],cv[4],cv[5]); upk2(accp[r][3],cv[6],cv[7]);
#pragma unroll
        for (int c=0;c<8;c++){
            int gn = n0 + (tx<<3) + c;
            if (gn >= N) continue;
            C[(size_t)gm*N+gn] = fmaf(alpha, cv[c], c0) + ((gm==gn)?diag:0.f);
        }
    }
}

// ---------------- X0 = 2I - M (elementwise) ----------------
__global__ void k_x0(const float* __restrict__ Mm, float* __restrict__ X){
    size_t idx = (size_t)blockIdx.x*256 + threadIdx.x;
    if (idx >= (size_t)NB*NT*NT) return;
    int w = (int)(idx % (NT*NT));
    int i = w / NT, j = w - i*NT;
    X[idx] = ((i==j)?2.f:0.f) - Mm[idx];
}

// ---------------- fused ADMM, f32x2 packed rows ----------------
// Thread ii owns row pairs (ii, ii+49) and (ii+98, ii+147), element-interleaved
// in smem as float2 with stride STR2=198 float2s (word-offsets conflict-free).
#define STR2 198
#define SRSTR 204
__global__ void __launch_bounds__(343,1) k_admm(const float* __restrict__ Minv,
                       const float* __restrict__ P, float* __restrict__ Cf){
    extern __shared__ float sm[];
    float* sM2 = sm;                       // 98 * STR2 float2 = 98*198*2 floats
    float* sR  = sm + 2*98*STR2;           // 49 * SRSTR floats
    int b = blockIdx.y, tb = blockIdx.x;
    int tid = threadIdx.x;
    int ii = tid/7, nn = tid - ii*7;
    const float* Mb = Minv + (size_t)b*NT*NT;
    for (int idx = tid; idx < NT*NT; idx += 343){
        int r = idx/NT, c = idx - r*NT;
        int half = (r/49)&1, pr = r/98, io = r - (r/49)*49;
        sM2[ ((size_t)(pr*49+io)*STR2 + c)*2 + half ] = Mb[idx];
    }
    float p[7][4], s[7][4];
    const float* Pb = P + ((size_t)b*NT + tb*49)*NT;
#pragma unroll
    for (int t=0;t<7;t++)
#pragma unroll
        for (int r=0;r<4;r++)
            p[t][r] = Pb[(size_t)(nn*7+t)*NT + ii + 49*r];
    __syncthreads();
    const ulonglong2* mp0 = (const ulonglong2*)(sM2 + (size_t)ii*STR2*2);
    const ulonglong2* mp1 = (const ulonglong2*)(sM2 + (size_t)(49+ii)*STR2*2);
    for (int it=0; it<50; it++){
#pragma unroll
        for (int t=0;t<7;t++){
            int base = (nn*7+t)*SRSTR + ii;
#pragma unroll
            for (int r=0;r<4;r++){
                float rv;
                if (it==0) rv = -p[t][r];
                else { float sv = s[t][r]; rv = 2.f*clipf(sv) - sv - p[t][r]; }
                sR[base + 49*r] = rv;
            }
        }
        __syncthreads();
        ull accp[7][2] = {};
        for (int j=0;j<NT;j+=4){
            ulonglong2 ma = mp0[j>>1];
            ulonglong2 mb = mp0[(j>>1)+1];
            ulonglong2 na = mp1[j>>1];
            ulonglong2 nb = mp1[(j>>1)+1];
#pragma unroll
            for (int t=0;t<7;t++){
                float4 rv = *(const float4*)(sR + (nn*7+t)*SRSTR + j);
                ull r0 = pk2(rv.x,rv.x), r1 = pk2(rv.y,rv.y);
                ull r2 = pk2(rv.z,rv.z), r3 = pk2(rv.w,rv.w);
                accp[t][0] = fma2(ma.x, r0, accp[t][0]);
                accp[t][0] = fma2(ma.y, r1, accp[t][0]);
                accp[t][0] = fma2(mb.x, r2, accp[t][0]);
                accp[t][0] = fma2(mb.y, r3, accp[t][0]);
                accp[t][1] = fma2(na.x, r0, accp[t][1]);
                accp[t][1] = fma2(na.y, r1, accp[t][1]);
                accp[t][1] = fma2(nb.x, r2, accp[t][1]);
                accp[t][1] = fma2(nb.y, r3, accp[t][1]);
            }
        }
#pragma unroll
        for (int t=0;t<7;t++){
            float a0,a1,a2,a3;
            upk2(accp[t][0], a0, a1);
            upk2(accp[t][1], a2, a3);
            if (it==0){ s[t][0]=a0; s[t][1]=a1; s[t][2]=a2; s[t][3]=a3; }
            else {
                s[t][0] = a0 + s[t][0] - clipf(s[t][0]);
                s[t][1] = a1 + s[t][1] - clipf(s[t][1]);
                s[t][2] = a2 + s[t][2] - clipf(s[t][2]);
                s[t][3] = a3 + s[t][3] - clipf(s[t][3]);
            }
        }
        __syncthreads();
    }
    // z = clip(s) -> sR, rowwise normalize, write coeffs
#pragma unroll
    for (int t=0;t<7;t++){
        int base = (nn*7+t)*SRSTR + ii;
#pragma unroll
        for (int r=0;r<4;r++)
            sR[base + 49*r] = clipf(s[t][r]);
    }
    __syncthreads();
    if (tid < 49){
        float sum = 0.f;
        for (int j=0;j<NT;j++) sum += sR[tid*SRSTR+j];
        sM2[tid] = 1.f/(sum + 1e-10f);
    }
    __syncthreads();
    float* Cb = Cf + ((size_t)b*NT + tb*49)*NT;
#pragma unroll
    for (int t=0;t<7;t++){
        int tk = nn*7+t;
        float inv = sM2[tk];
#pragma unroll
        for (int r=0;r<4;r++)
            Cb[(size_t)tk*NT + ii + 49*r] = sR[tk*SRSTR + ii + 49*r]*inv;
    }
}

// ---------------- pool: mean over tokens ----------------
__global__ void k_pool(const float* __restrict__ O, float* __restrict__ pooled){
    int b = blockIdx.x, tid = threadIdx.x;
    const float* Ob = O + (size_t)b*NT*DM;
    float s0=0.f, s1=0.f;
    for (int n=0;n<NT;n++){ s0 += Ob[(size_t)n*DM+tid]; s1 += Ob[(size_t)n*DM+256+tid]; }
    pooled[b*DM+tid] = s0/(float)NT;
    pooled[b*DM+256+tid] = s1/(float)NT;
}

// ---------------- head: LN + GEMM(512x1000) + softmax ----------------
__global__ void k_head(const float* __restrict__ pooled, const float* __restrict__ g,
                       const float* __restrict__ bb, const float* __restrict__ W,
                       const float* __restrict__ wb, float* __restrict__ out){
    int b = blockIdx.x, tid = threadIdx.x;
    __shared__ float xs[512]; __shared__ float red[256]; __shared__ float smu, srs, sred;
    float v0 = pooled[b*DM+tid], v1 = pooled[b*DM+256+tid];
    red[tid] = v0+v1; __syncthreads();
    for (int o=128;o;o>>=1){ if (tid<o) red[tid]+=red[tid+o]; __syncthreads(); }
    if (!tid) smu = red[0]/512.f;
    __syncthreads();
    float mu = smu, d0=v0-mu, d1=v1-mu;
    red[tid] = d0*d0+d1*d1; __syncthreads();
    for (int o=128;o;o>>=1){ if (tid<o) red[tid]+=red[tid+o]; __syncthreads(); }
    if (!tid) srs = rsqrtf(red[0]/512.f + 1e-5f);
    __syncthreads();
    float rs = srs;
    xs[tid] = d0*rs*g[tid]+bb[tid];
    xs[tid+256] = d1*rs*g[tid+256]+bb[tid+256];
    __syncthreads();
    float lg[4];
#pragma unroll
    for (int c4=0;c4<4;c4++){
        int c = c4*256 + tid;
        float acc = 0.f;
        if (c < NC){
            for (int k=0;k<512;k++) acc = fmaf(xs[k], W[(size_t)k*NC+c], acc);
            acc += wb[c];
        } else acc = -1e30f;
        lg[c4] = acc;
    }
    float mx = fmaxf(fmaxf(lg[0],lg[1]),fmaxf(lg[2],lg[3]));
    red[tid] = mx; __syncthreads();
    for (int o=128;o;o>>=1){ if (tid<o) red[tid]=fmaxf(red[tid],red[tid+o]); __syncthreads(); }
    if (!tid) sred = red[0];
    __syncthreads();
    mx = sred;
    float es = 0.f;
#pragma unroll
    for (int c4=0;c4<4;c4++){ lg[c4] = __expf(lg[c4]-mx); if (c4*256+tid < NC) es += lg[c4]; }
    red[tid] = es; __syncthreads();
    for (int o=128;o;o>>=1){ if (tid<o) red[tid]+=red[tid+o]; __syncthreads(); }
    if (!tid) sred = red[0];
    __syncthreads();
    float inv = 1.f/sred;
#pragma unroll
    for (int c4=0;c4<4;c4++){ int c = c4*256+tid; if (c < NC) out[(size_t)b*NC+c] = lg[c4]*inv; }
}

extern "C" void kernel_launch(void* const* d_in, const int* in_sizes, int n_in,
                              void* d_out, int out_size){
    const float* img   = (const float*)d_in[0];
    const float* lpg   = (const float*)d_in[1];
    const float* lpb   = (const float*)d_in[2];
    const float* wq_w  = (const float*)d_in[3];
    const float* wq_b  = (const float*)d_in[4];
    const float* lnq_g = (const float*)d_in[5];
    const float* lnq_b = (const float*)d_in[6];
    const float* wv_w  = (const float*)d_in[7];
    const float* wv_b  = (const float*)d_in[8];
    const float* lnv_g = (const float*)d_in[9];
    const float* lnv_b = (const float*)d_in[10];
    const float* pos   = (const float*)d_in[11];
    const float* mlg   = (const float*)d_in[12];
    const float* mlb   = (const float*)d_in[13];
    const float* mlw   = (const float*)d_in[14];
    const float* mlwb  = (const float*)d_in[15];
    float* out = (float*)d_out;

    float *pX,*pQ,*pV,*pM,*pXa,*pXb,*pT,*pP,*pCf,*pO,*pPool;
    cudaGetSymbolAddress((void**)&pX, g_X);
    cudaGetSymbolAddress((void**)&pQ, g_Q);
    cudaGetSymbolAddress((void**)&pV, g_V);
    cudaGetSymbolAddress((void**)&pM, g_M);
    cudaGetSymbolAddress((void**)&pXa, g_Xa);
    cudaGetSymbolAddress((void**)&pXb, g_Xb);
    cudaGetSymbolAddress((void**)&pT, g_T);
    cudaGetSymbolAddress((void**)&pP, g_P);
    cudaGetSymbolAddress((void**)&pCf, g_Cf);
    cudaGetSymbolAddress((void**)&pO, g_O);
    cudaGetSymbolAddress((void**)&pPool, g_pool);

    const int admm_smem = (2*98*STR2 + 49*SRSTR)*4;
    static int s_attr_done = 0;
    if (!s_attr_done){
        cudaFuncSetAttribute(k_admm, cudaFuncAttributeMaxDynamicSharedMemorySize, admm_smem);
        s_attr_done = 1;
    }

    // 1. patchify + LN + pos
    k_patchify<<<MTOT, 256>>>(img, lpg, lpb, pos);
    // 2. fused Q/V projections + LN (V scaled by 1/196)
    k_proj<<<dim3(DM/128, MTOT/128, 2), 256>>>(pX, wq_w, wq_b, wv_w, wv_b, pQ, pV);
    k_ln512<<<MTOT, 256>>>(pQ, lnq_g, lnq_b, 1.f);
    k_ln512<<<MTOT, 256>>>(pV, lnv_g, lnv_b, 1.f/(float)NT);
    // 3. M = I + 2VV^T ; p = -2 Q V^T + 1/196 ; X0 = 2I - M
    dim3 gNT(2,2,NB);
    k_bgemm<<<gNT,256>>>(pV, pV, pM, NT, NT, DM, 1,  2.f, 0.f, 1.f);
    k_bgemm<<<gNT,256>>>(pQ, pV, pP, NT, NT, DM, 1, -2.f, 1.f/(float)NT, 0.f);
    k_x0<<<(NB*NT*NT + 255)/256, 256>>>(pM, pXa);
    // 4. Newton-Schulz x3: T = 2I - M@X ; X' = X@T
    float* Xc = pXa; float* Xn = pXb;
    for (int i=0;i<3;i++){
        k_bgemm<<<gNT,256>>>(pM, Xc, pT, NT, NT, NT, 0, -1.f, 0.f, 2.f);
        k_bgemm<<<gNT,256>>>(Xc, pT, Xn, NT, NT, NT, 0,  1.f, 0.f, 0.f);
        float* t = Xc; Xc = Xn; Xn = t;
    }
    // 5. ADMM (fused, 50 iters) -> normalized coeffs
    k_admm<<<dim3(4,NB), 343, admm_smem>>>(Xc, pP, pCf);
    // 6. out = coeffs @ V
    k_bgemm<<<dim3(4,2,NB),256>>>(pCf, pV, pO, NT, DM, NT, 0, 1.f, 0.f, 0.f);
    // 7. pool + head
    k_pool<<<NB, 256>>>(pO, pPool);
    k_head<<<NB, 256>>>(pPool, mlg, mlb, mlw, mlwb, out);
}

// round 6
// speedup vs baseline: 1.5308x; 1.5308x over previous
#include <cuda_runtime.h>

#define NB 32
#define NT 196
#define PD 768
#define DM 512
#define NC 1000
#define MTOT (NB*NT)

__device__ float g_X [(size_t)MTOT*PD];
__device__ float g_Q [(size_t)MTOT*DM];
__device__ float g_V [(size_t)MTOT*DM];
__device__ float g_M [(size_t)NB*NT*NT];
__device__ float g_Xa[(size_t)NB*NT*NT];
__device__ float g_Xb[(size_t)NB*NT*NT];
__device__ float g_T [(size_t)NB*NT*NT];
__device__ float g_P [(size_t)NB*NT*NT];
__device__ float g_Cf[(size_t)NB*NT*NT];
__device__ float g_O [(size_t)MTOT*DM];
__device__ float g_pool[NB*DM];

__device__ __forceinline__ float clipf(float x){ return fminf(fmaxf(x, 0.f), 1.f); }

__device__ __forceinline__ float4 ld4g(const float* p, int rem){
    if (rem >= 4) return *(const float4*)p;
    float4 v = make_float4(0.f,0.f,0.f,0.f);
    if (rem > 0) v.x = p[0];
    if (rem > 1) v.y = p[1];
    if (rem > 2) v.z = p[2];
    return v;
}

// ---------------- patchify + LN(768) + pos ----------------
__global__ void k_patchify(const float* __restrict__ img, const float* __restrict__ g,
                           const float* __restrict__ bb, const float* __restrict__ pos){
    int bn = blockIdx.x, b = bn / NT, n = bn % NT;
    int hh = n / 14, ww = n % 14;
    int tid = threadIdx.x, ph = tid >> 4, pw = tid & 15;
    const float* ib = img + (size_t)b*3*224*224 + (size_t)(hh*16+ph)*224 + (ww*16+pw);
    float v0 = ib[0], v1 = ib[224*224], v2 = ib[2*224*224];
    __shared__ float red[256]; __shared__ float smu, srs;
    red[tid] = v0+v1+v2; __syncthreads();
    for (int o=128;o;o>>=1){ if (tid<o) red[tid]+=red[tid+o]; __syncthreads(); }
    if (!tid) smu = red[0]/768.f;
    __syncthreads();
    float mu = smu, d0=v0-mu, d1=v1-mu, d2=v2-mu;
    red[tid] = d0*d0+d1*d1+d2*d2; __syncthreads();
    for (int o=128;o;o>>=1){ if (tid<o) red[tid]+=red[tid+o]; __syncthreads(); }
    if (!tid) srs = rsqrtf(red[0]/768.f + 1e-5f);
    __syncthreads();
    float rs = srs;
    float* xo = g_X + (size_t)bn*PD;
    const float* pp = pos + (size_t)n*PD;
    int q = tid;     xo[q] = d0*rs*g[q] + bb[q] + pp[q];
    q = 256+tid;     xo[q] = d1*rs*g[q] + bb[q] + pp[q];
    q = 512+tid;     xo[q] = d2*rs*g[q] + bb[q] + pp[q];
}

// ---------------- fused projections: z=0 -> Q, z=1 -> V. 128x128, double-buffered ----------------
__global__ void __launch_bounds__(256,2) k_proj(const float* __restrict__ X,
                       const float* __restrict__ Wq, const float* __restrict__ bq,
                       const float* __restrict__ Wv, const float* __restrict__ bv,
                       float* __restrict__ Qo, float* __restrict__ Vo){
    __shared__ float As[2][16][128];
    __shared__ float Bs[2][16][128];
    const float* B   = blockIdx.z ? Wv : Wq;
    const float* bia = blockIdx.z ? bv : bq;
    float* C         = blockIdx.z ? Vo : Qo;
    const int Nv = DM, Kv = PD;
    int tid = threadIdx.x;
    int m0 = blockIdx.y<<7, n0 = blockIdx.x<<7;
    int ty = tid>>4, tx = tid&15;
    int aRow = tid>>1, aK = (tid&1)<<3;
    int bK = tid>>4, bN = (tid&15)<<3;
    const float* Ap = X + (size_t)(m0+aRow)*Kv + aK;
    const float* Bp = B + (size_t)bK*Nv + n0 + bN;
    float4 pa0 = *(const float4*)(Ap);
    float4 pa1 = *(const float4*)(Ap+4);
    float4 pb0 = *(const float4*)(Bp);
    float4 pb1 = *(const float4*)(Bp+4);
    As[0][aK+0][aRow]=pa0.x; As[0][aK+1][aRow]=pa0.y; As[0][aK+2][aRow]=pa0.z; As[0][aK+3][aRow]=pa0.w;
    As[0][aK+4][aRow]=pa1.x; As[0][aK+5][aRow]=pa1.y; As[0][aK+6][aRow]=pa1.z; As[0][aK+7][aRow]=pa1.w;
    *(float4*)&Bs[0][bK][bN] = pb0; *(float4*)&Bs[0][bK][bN+4] = pb1;
    __syncthreads();
    float acc[8][8] = {};
    const int NP = Kv>>4;
    int buf = 0;
    for (int p=0;p<NP;p++){
        bool more = (p+1)<NP;
        if (more){
            int k0 = (p+1)<<4;
            pa0 = *(const float4*)(Ap + k0);
            pa1 = *(const float4*)(Ap + k0 + 4);
            pb0 = *(const float4*)(Bp + (size_t)k0*Nv);
            pb1 = *(const float4*)(Bp + (size_t)k0*Nv + 4);
        }
#pragma unroll
        for (int kk=0;kk<16;kk++){
            float4 a0=*(const float4*)&As[buf][kk][ty<<3];
            float4 a1=*(const float4*)&As[buf][kk][(ty<<3)+4];
            float4 b0=*(const float4*)&Bs[buf][kk][tx<<3];
            float4 b1=*(const float4*)&Bs[buf][kk][(tx<<3)+4];
            float av[8]={a0.x,a0.y,a0.z,a0.w,a1.x,a1.y,a1.z,a1.w};
            float bw[8]={b0.x,b0.y,b0.z,b0.w,b1.x,b1.y,b1.z,b1.w};
#pragma unroll
            for (int r=0;r<8;r++)
#pragma unroll
                for (int c=0;c<8;c++)
                    acc[r][c] = fmaf(av[r], bw[c], acc[r][c]);
        }
        if (more){
            int nb = buf^1;
            As[nb][aK+0][aRow]=pa0.x; As[nb][aK+1][aRow]=pa0.y; As[nb][aK+2][aRow]=pa0.z; As[nb][aK+3][aRow]=pa0.w;
            As[nb][aK+4][aRow]=pa1.x; As[nb][aK+5][aRow]=pa1.y; As[nb][aK+6][aRow]=pa1.z; As[nb][aK+7][aRow]=pa1.w;
            *(float4*)&Bs[nb][bK][bN] = pb0; *(float4*)&Bs[nb][bK][bN+4] = pb1;
            __syncthreads();
            buf = nb;
        }
    }
    float4 bi0 = *(const float4*)(bia + n0 + (tx<<3));
    float4 bi1 = *(const float4*)(bia + n0 + (tx<<3) + 4);
#pragma unroll
    for (int r=0;r<8;r++){
        int gm = m0 + (ty<<3) + r;
        float4 o0 = make_float4(acc[r][0]+bi0.x, acc[r][1]+bi0.y, acc[r][2]+bi0.z, acc[r][3]+bi0.w);
        float4 o1 = make_float4(acc[r][4]+bi1.x, acc[r][5]+bi1.y, acc[r][6]+bi1.z, acc[r][7]+bi1.w);
        *(float4*)(C + (size_t)gm*Nv + n0 + (tx<<3)) = o0;
        *(float4*)(C + (size_t)gm*Nv + n0 + (tx<<3) + 4) = o1;
    }
}

// ---------------- in-place rowwise LN(512), then *scale ----------------
__global__ void k_ln512(float* __restrict__ y0, const float* __restrict__ g,
                        const float* __restrict__ bb, float scale){
    float* y = y0 + (size_t)blockIdx.x*DM;
    int tid = threadIdx.x;
    float v0 = y[tid], v1 = y[tid+256];
    __shared__ float red[256]; __shared__ float smu, srs;
    red[tid] = v0+v1; __syncthreads();
    for (int o=128;o;o>>=1){ if (tid<o) red[tid]+=red[tid+o]; __syncthreads(); }
    if (!tid) smu = red[0]/512.f;
    __syncthreads();
    float mu = smu, d0=v0-mu, d1=v1-mu;
    red[tid] = d0*d0+d1*d1; __syncthreads();
    for (int o=128;o;o>>=1){ if (tid<o) red[tid]+=red[tid+o]; __syncthreads(); }
    if (!tid) srs = rsqrtf(red[0]/512.f + 1e-5f);
    __syncthreads();
    float rs = srs;
    y[tid]     = (d0*rs*g[tid]     + bb[tid])     * scale;
    y[tid+256] = (d1*rs*g[tid+256] + bb[tid+256]) * scale;
}

// ---------------- batched GEMM, 98x98 tiles (exact fit for 196), 196 thr, 7x7 micro ----------------
// C[196,196] = alpha*A@op(B) + c0 + diag*I. A:[196,K]. transB: B:[196,K]; NN: B:[K,196].
__global__ void __launch_bounds__(196,2) k_bgemm98(const float* __restrict__ A0,
                        const float* __restrict__ B0, float* __restrict__ C0,
                        int K, int transB, float alpha, float c0, float diag){
    __shared__ float As[2][16][100];
    __shared__ float Bs[2][16][100];
    const float* A = A0 + (size_t)blockIdx.z*NT*K;
    const float* B = B0 + (size_t)blockIdx.z*NT*K;
    float* C = C0 + (size_t)blockIdx.z*NT*NT;
    int tid = threadIdx.x;
    int m0 = blockIdx.y*98, n0 = blockIdx.x*98;
    int ty = tid/14, tx = tid - ty*14;
    int lr = tid>>1, lk = (tid&1)<<3;     // A/transB-B loader: row lr (0..97), k-offset lk (0/8)
    const int NP = (K+15)>>4;
    float a_pf[8], b_pf[8];
    // prefetch tile 0
    {
        const float* Ap = A + (size_t)(m0+lr)*K + lk;
#pragma unroll
        for (int j=0;j<8;j++) a_pf[j] = (lk+j < K) ? Ap[j] : 0.f;
        if (transB){
            const float* Bp = B + (size_t)(n0+lr)*K + lk;
#pragma unroll
            for (int j=0;j<8;j++) b_pf[j] = (lk+j < K) ? Bp[j] : 0.f;
        } else {
#pragma unroll
            for (int e=0;e<8;e++){
                int idx = tid + 196*e, kk = idx/98, n = idx - kk*98;
                b_pf[e] = (kk < K) ? B[(size_t)kk*NT + n0 + n] : 0.f;
            }
        }
    }
#pragma unroll
    for (int j=0;j<8;j++) As[0][lk+j][lr] = a_pf[j];
    if (transB){
#pragma unroll
        for (int j=0;j<8;j++) Bs[0][lk+j][lr] = b_pf[j];
    } else {
#pragma unroll
        for (int e=0;e<8;e++){
            int idx = tid + 196*e, kk = idx/98, n = idx - kk*98;
            Bs[0][kk][n] = b_pf[e];
        }
    }
    __syncthreads();
    float acc[7][7] = {};
    int buf = 0;
    for (int p=0;p<NP;p++){
        bool more = (p+1)<NP;
        if (more){
            int k0 = (p+1)<<4;
            const float* Ap = A + (size_t)(m0+lr)*K + k0 + lk;
#pragma unroll
            for (int j=0;j<8;j++) a_pf[j] = (k0+lk+j < K) ? Ap[j] : 0.f;
            if (transB){
                const float* Bp = B + (size_t)(n0+lr)*K + k0 + lk;
#pragma unroll
                for (int j=0;j<8;j++) b_pf[j] = (k0+lk+j < K) ? Bp[j] : 0.f;
            } else {
#pragma unroll
                for (int e=0;e<8;e++){
                    int idx = tid + 196*e, kk = idx/98, n = idx - kk*98;
                    b_pf[e] = (k0+kk < K) ? B[(size_t)(k0+kk)*NT + n0 + n] : 0.f;
                }
            }
        }
#pragma unroll
        for (int kk=0;kk<16;kk++){
            float a[7], b[7];
#pragma unroll
            for (int r=0;r<7;r++) a[r] = As[buf][kk][ty*7+r];
#pragma unroll
            for (int c=0;c<7;c++) b[c] = Bs[buf][kk][tx*7+c];
#pragma unroll
            for (int r=0;r<7;r++)
#pragma unroll
                for (int c=0;c<7;c++)
                    acc[r][c] = fmaf(a[r], b[c], acc[r][c]);
        }
        if (more){
            int nb = buf^1;
#pragma unroll
            for (int j=0;j<8;j++) As[nb][lk+j][lr] = a_pf[j];
            if (transB){
#pragma unroll
                for (int j=0;j<8;j++) Bs[nb][lk+j][lr] = b_pf[j];
            } else {
#pragma unroll
                for (int e=0;e<8;e++){
                    int idx = tid + 196*e, kk = idx/98, n = idx - kk*98;
                    Bs[nb][kk][n] = b_pf[e];
                }
            }
            __syncthreads();
            buf = nb;
        }
    }
#pragma unroll
    for (int r=0;r<7;r++){
        int gm = m0 + ty*7 + r;
#pragma unroll
        for (int c=0;c<7;c++){
            int gn = n0 + tx*7 + c;
            C[(size_t)gm*NT+gn] = fmaf(alpha, acc[r][c], c0) + ((gm==gn)?diag:0.f);
        }
    }
}

// ---------------- batched GEMM 128x128 (used for out = Cf@V) ----------------
__global__ void __launch_bounds__(256,2) k_bgemm(const float* __restrict__ A0, const float* __restrict__ B0,
                        float* __restrict__ C0, int M, int N, int K, int transB,
                        float alpha, float c0, float diag){
    __shared__ float As[2][16][128];
    __shared__ float Bs[2][16][128];
    const float* A = A0 + (size_t)blockIdx.z*M*K;
    const float* B = B0 + (size_t)blockIdx.z*((size_t)N*K);
    float* C = C0 + (size_t)blockIdx.z*M*N;
    int tid = threadIdx.x;
    int m0 = blockIdx.y<<7, n0 = blockIdx.x<<7;
    int ty = tid>>4, tx = tid&15;
    int aRow = tid>>1, aK = (tid&1)<<3;
    bool aok = (m0+aRow) < M;
    int bRT = tid>>1, bKT = (tid&1)<<3;
    bool bokT = (n0+bRT) < N;
    int bK = tid>>4, bN = (tid&15)<<3;
    const int NP = (K+15)>>4;
    float4 pa0,pa1,pb0,pb1;
    {
        const float* Ap = A + (size_t)(m0+aRow)*K + aK;
        int remA = aok ? (K - aK) : 0;
        pa0 = ld4g(Ap, remA); pa1 = ld4g(Ap+4, remA-4);
        if (transB){
            const float* Bp = B + (size_t)(n0+bRT)*K + bKT;
            int remB = bokT ? (K - bKT) : 0;
            pb0 = ld4g(Bp, remB); pb1 = ld4g(Bp+4, remB-4);
        } else {
            const float* Bp = B + (size_t)bK*N + n0 + bN;
            int remB = (bK < K) ? (N-(n0+bN)) : 0;
            pb0 = ld4g(Bp, remB); pb1 = ld4g(Bp+4, remB-4);
        }
    }
    As[0][aK+0][aRow]=pa0.x; As[0][aK+1][aRow]=pa0.y; As[0][aK+2][aRow]=pa0.z; As[0][aK+3][aRow]=pa0.w;
    As[0][aK+4][aRow]=pa1.x; As[0][aK+5][aRow]=pa1.y; As[0][aK+6][aRow]=pa1.z; As[0][aK+7][aRow]=pa1.w;
    if (transB){
        Bs[0][bKT+0][bRT]=pb0.x; Bs[0][bKT+1][bRT]=pb0.y; Bs[0][bKT+2][bRT]=pb0.z; Bs[0][bKT+3][bRT]=pb0.w;
        Bs[0][bKT+4][bRT]=pb1.x; Bs[0][bKT+5][bRT]=pb1.y; Bs[0][bKT+6][bRT]=pb1.z; Bs[0][bKT+7][bRT]=pb1.w;
    } else {
        *(float4*)&Bs[0][bK][bN] = pb0; *(float4*)&Bs[0][bK][bN+4] = pb1;
    }
    __syncthreads();
    float acc[8][8] = {};
    int buf = 0;
    for (int p=0;p<NP;p++){
        bool more = (p+1)<NP;
        if (more){
            int k0 = (p+1)<<4;
            const float* Ap = A + (size_t)(m0+aRow)*K + k0 + aK;
            int remA = aok ? (K - (k0+aK)) : 0;
            pa0 = ld4g(Ap, remA); pa1 = ld4g(Ap+4, remA-4);
            if (transB){
                const float* Bp = B + (size_t)(n0+bRT)*K + k0 + bKT;
                int remB = bokT ? (K - (k0+bKT)) : 0;
                pb0 = ld4g(Bp, remB); pb1 = ld4g(Bp+4, remB-4);
            } else {
                const float* Bp = B + (size_t)(k0+bK)*N + n0 + bN;
                int remB = ((k0+bK) < K) ? (N-(n0+bN)) : 0;
                pb0 = ld4g(Bp, remB); pb1 = ld4g(Bp+4, remB-4);
            }
        }
#pragma unroll
        for (int kk=0;kk<16;kk++){
            float4 a0=*(const float4*)&As[buf][kk][ty<<3];
            float4 a1=*(const float4*)&As[buf][kk][(ty<<3)+4];
            float4 b0=*(const float4*)&Bs[buf][kk][tx<<3];
            float4 b1=*(const float4*)&Bs[buf][kk][(tx<<3)+4];
            float av[8]={a0.x,a0.y,a0.z,a0.w,a1.x,a1.y,a1.z,a1.w};
            float bw[8]={b0.x,b0.y,b0.z,b0.w,b1.x,b1.y,b1.z,b1.w};
#pragma unroll
            for (int r=0;r<8;r++)
#pragma unroll
                for (int c=0;c<8;c++)
                    acc[r][c] = fmaf(av[r], bw[c], acc[r][c]);
        }
        if (more){
            int nb = buf^1;
            As[nb][aK+0][aRow]=pa0.x; As[nb][aK+1][aRow]=pa0.y; As[nb][aK+2][aRow]=pa0.z; As[nb][aK+3][aRow]=pa0.w;
            As[nb][aK+4][aRow]=pa1.x; As[nb][aK+5][aRow]=pa1.y; As[nb][aK+6][aRow]=pa1.z; As[nb][aK+7][aRow]=pa1.w;
            if (transB){
                Bs[nb][bKT+0][bRT]=pb0.x; Bs[nb][bKT+1][bRT]=pb0.y; Bs[nb][bKT+2][bRT]=pb0.z; Bs[nb][bKT+3][bRT]=pb0.w;
                Bs[nb][bKT+4][bRT]=pb1.x; Bs[nb][bKT+5][bRT]=pb1.y; Bs[nb][bKT+6][bRT]=pb1.z; Bs[nb][bKT+7][bRT]=pb1.w;
            } else {
                *(float4*)&Bs[nb][bK][bN] = pb0; *(float4*)&Bs[nb][bK][bN+4] = pb1;
            }
            __syncthreads();
            buf = nb;
        }
    }
#pragma unroll
    for (int r=0;r<8;r++){
        int gm = m0 + (ty<<3) + r;
        if (gm >= M) continue;
#pragma unroll
        for (int c=0;c<8;c++){
            int gn = n0 + (tx<<3) + c;
            if (gn >= N) continue;
            C[(size_t)gm*N+gn] = fmaf(alpha, acc[r][c], c0) + ((gm==gn)?diag:0.f);
        }
    }
}

// ---------------- X0 = 2I - M (elementwise) ----------------
__global__ void k_x0(const float* __restrict__ Mm, float* __restrict__ X){
    size_t idx = (size_t)blockIdx.x*256 + threadIdx.x;
    if (idx >= (size_t)NB*NT*NT) return;
    int w = (int)(idx % (NT*NT));
    int i = w / NT, j = w - i*NT;
    X[idx] = ((i==j)?2.f:0.f) - Mm[idx];
}

// ---------------- fused ADMM: 50 iters, conflict-free smem layout (R3 proven) ----------------
#define SMSTR 204
__global__ void k_admm(const float* __restrict__ Minv, const float* __restrict__ P,
                       float* __restrict__ Cf){
    extern __shared__ float sm[];
    float* sM = sm;                   // 196 x SMSTR
    float* sR = sm + NT*SMSTR;        // 49 x SMSTR
    int b = blockIdx.y, tb = blockIdx.x;
    int tid = threadIdx.x;
    int ii = tid/7, nn = tid - ii*7;
    const float* Mb = Minv + (size_t)b*NT*NT;
    for (int idx = tid; idx < NT*NT; idx += 343){
        int r = idx/NT, c = idx - r*NT;
        sM[r*SMSTR + c] = Mb[idx];
    }
    float p[7][4], s[7][4];
    const float* Pb = P + ((size_t)b*NT + tb*49)*NT;
#pragma unroll
    for (int t=0;t<7;t++)
#pragma unroll
        for (int r=0;r<4;r++)
            p[t][r] = Pb[(size_t)(nn*7+t)*NT + ii + 49*r];
    __syncthreads();
    const float* m0p = sM + (size_t)ii*SMSTR;
    const float* m1p = sM + (size_t)(ii+49)*SMSTR;
    const float* m2p = sM + (size_t)(ii+98)*SMSTR;
    const float* m3p = sM + (size_t)(ii+147)*SMSTR;
    for (int it=0; it<50; it++){
#pragma unroll
        for (int t=0;t<7;t++){
            int base = (nn*7+t)*SMSTR + ii;
#pragma unroll
            for (int r=0;r<4;r++){
                float rv;
                if (it==0) rv = -p[t][r];
                else { float sv = s[t][r]; rv = 2.f*clipf(sv) - sv - p[t][r]; }
                sR[base + 49*r] = rv;
            }
        }
        __syncthreads();
        float acc[7][4] = {};
        for (int j=0;j<NT;j+=4){
            float4 m0 = *(const float4*)(m0p+j);
            float4 m1 = *(const float4*)(m1p+j);
            float4 m2 = *(const float4*)(m2p+j);
            float4 m3 = *(const float4*)(m3p+j);
#pragma unroll
            for (int t=0;t<7;t++){
                float4 rv = *(const float4*)(sR + (nn*7+t)*SMSTR + j);
                acc[t][0]=fmaf(m0.x,rv.x,fmaf(m0.y,rv.y,fmaf(m0.z,rv.z,fmaf(m0.w,rv.w,acc[t][0]))));
                acc[t][1]=fmaf(m1.x,rv.x,fmaf(m1.y,rv.y,fmaf(m1.z,rv.z,fmaf(m1.w,rv.w,acc[t][1]))));
                acc[t][2]=fmaf(m2.x,rv.x,fmaf(m2.y,rv.y,fmaf(m2.z,rv.z,fmaf(m2.w,rv.w,acc[t][2]))));
                acc[t][3]=fmaf(m3.x,rv.x,fmaf(m3.y,rv.y,fmaf(m3.z,rv.z,fmaf(m3.w,rv.w,acc[t][3]))));
            }
        }
#pragma unroll
        for (int t=0;t<7;t++)
#pragma unroll
            for (int r=0;r<4;r++)
                s[t][r] = (it==0) ? acc[t][r] : acc[t][r] + s[t][r] - clipf(s[t][r]);
        __syncthreads();
    }
#pragma unroll
    for (int t=0;t<7;t++){
        int base = (nn*7+t)*SMSTR + ii;
#pragma unroll
        for (int r=0;r<4;r++)
            sR[base + 49*r] = clipf(s[t][r]);
    }
    __syncthreads();
    if (tid < 49){
        float sum = 0.f;
        for (int j=0;j<NT;j++) sum += sR[tid*SMSTR+j];
        sM[tid] = 1.f/(sum + 1e-10f);
    }
    __syncthreads();
    float* Cb = Cf + ((size_t)b*NT + tb*49)*NT;
#pragma unroll
    for (int t=0;t<7;t++){
        int tk = nn*7+t;
        float inv = sM[tk];
#pragma unroll
        for (int r=0;r<4;r++)
            Cb[(size_t)tk*NT + ii + 49*r] = sR[tk*SMSTR + ii + 49*r]*inv;
    }
}

// ---------------- pool: mean over tokens ----------------
__global__ void k_pool(const float* __restrict__ O, float* __restrict__ pooled){
    int b = blockIdx.x, tid = threadIdx.x;
    const float* Ob = O + (size_t)b*NT*DM;
    float s0=0.f, s1=0.f;
    for (int n=0;n<NT;n++){ s0 += Ob[(size_t)n*DM+tid]; s1 += Ob[(size_t)n*DM+256+tid]; }
    pooled[b*DM+tid] = s0/(float)NT;
    pooled[b*DM+256+tid] = s1/(float)NT;
}

// ---------------- head: LN + GEMM(512x1000) + softmax ----------------
__global__ void k_head(const float* __restrict__ pooled, const float* __restrict__ g,
                       const float* __restrict__ bb, const float* __restrict__ W,
                       const float* __restrict__ wb, float* __restrict__ out){
    int b = blockIdx.x, tid = threadIdx.x;
    __shared__ float xs[512]; __shared__ float red[256]; __shared__ float smu, srs, sred;
    float v0 = pooled[b*DM+tid], v1 = pooled[b*DM+256+tid];
    red[tid] = v0+v1; __syncthreads();
    for (int o=128;o;o>>=1){ if (tid<o) red[tid]+=red[tid+o]; __syncthreads(); }
    if (!tid) smu = red[0]/512.f;
    __syncthreads();
    float mu = smu, d0=v0-mu, d1=v1-mu;
    red[tid] = d0*d0+d1*d1; __syncthreads();
    for (int o=128;o;o>>=1){ if (tid<o) red[tid]+=red[tid+o]; __syncthreads(); }
    if (!tid) srs = rsqrtf(red[0]/512.f + 1e-5f);
    __syncthreads();
    float rs = srs;
    xs[tid] = d0*rs*g[tid]+bb[tid];
    xs[tid+256] = d1*rs*g[tid+256]+bb[tid+256];
    __syncthreads();
    float lg[4];
#pragma unroll
    for (int c4=0;c4<4;c4++){
        int c = c4*256 + tid;
        float acc = 0.f;
        if (c < NC){
            for (int k=0;k<512;k++) acc = fmaf(xs[k], W[(size_t)k*NC+c], acc);
            acc += wb[c];
        } else acc = -1e30f;
        lg[c4] = acc;
    }
    float mx = fmaxf(fmaxf(lg[0],lg[1]),fmaxf(lg[2],lg[3]));
    red[tid] = mx; __syncthreads();
    for (int o=128;o;o>>=1){ if (tid<o) red[tid]=fmaxf(red[tid],red[tid+o]); __syncthreads(); }
    if (!tid) sred = red[0];
    __syncthreads();
    mx = sred;
    float es = 0.f;
#pragma unroll
    for (int c4=0;c4<4;c4++){ lg[c4] = __expf(lg[c4]-mx); if (c4*256+tid < NC) es += lg[c4]; }
    red[tid] = es; __syncthreads();
    for (int o=128;o;o>>=1){ if (tid<o) red[tid]+=red[tid+o]; __syncthreads(); }
    if (!tid) sred = red[0];
    __syncthreads();
    float inv = 1.f/sred;
#pragma unroll
    for (int c4=0;c4<4;c4++){ int c = c4*256+tid; if (c < NC) out[(size_t)b*NC+c] = lg[c4]*inv; }
}

extern "C" void kernel_launch(void* const* d_in, const int* in_sizes, int n_in,
                              void* d_out, int out_size){
    const float* img   = (const float*)d_in[0];
    const float* lpg   = (const float*)d_in[1];
    const float* lpb   = (const float*)d_in[2];
    const float* wq_w  = (const float*)d_in[3];
    const float* wq_b  = (const float*)d_in[4];
    const float* lnq_g = (const float*)d_in[5];
    const float* lnq_b = (const float*)d_in[6];
    const float* wv_w  = (const float*)d_in[7];
    const float* wv_b  = (const float*)d_in[8];
    const float* lnv_g = (const float*)d_in[9];
    const float* lnv_b = (const float*)d_in[10];
    const float* pos   = (const float*)d_in[11];
    const float* mlg   = (const float*)d_in[12];
    const float* mlb   = (const float*)d_in[13];
    const float* mlw   = (const float*)d_in[14];
    const float* mlwb  = (const float*)d_in[15];
    float* out = (float*)d_out;

    float *pX,*pQ,*pV,*pM,*pXa,*pXb,*pT,*pP,*pCf,*pO,*pPool;
    cudaGetSymbolAddress((void**)&pX, g_X);
    cudaGetSymbolAddress((void**)&pQ, g_Q);
    cudaGetSymbolAddress((void**)&pV, g_V);
    cudaGetSymbolAddress((void**)&pM, g_M);
    cudaGetSymbolAddress((void**)&pXa, g_Xa);
    cudaGetSymbolAddress((void**)&pXb, g_Xb);
    cudaGetSymbolAddress((void**)&pT, g_T);
    cudaGetSymbolAddress((void**)&pP, g_P);
    cudaGetSymbolAddress((void**)&pCf, g_Cf);
    cudaGetSymbolAddress((void**)&pO, g_O);
    cudaGetSymbolAddress((void**)&pPool, g_pool);

    const int admm_smem = (NT*SMSTR + 49*SMSTR)*4;
    static int s_attr_done = 0;
    if (!s_attr_done){
        cudaFuncSetAttribute(k_admm, cudaFuncAttributeMaxDynamicSharedMemorySize, admm_smem);
        s_attr_done = 1;
    }

    // 1. patchify + LN + pos
    k_patchify<<<MTOT, 256>>>(img, lpg, lpb, pos);
    // 2. fused Q/V projections + LN (V scaled by 1/196)
    k_proj<<<dim3(DM/128, MTOT/128, 2), 256>>>(pX, wq_w, wq_b, wv_w, wv_b, pQ, pV);
    k_ln512<<<MTOT, 256>>>(pQ, lnq_g, lnq_b, 1.f);
    k_ln512<<<MTOT, 256>>>(pV, lnv_g, lnv_b, 1.f/(float)NT);
    // 3. M = I + 2VV^T ; p = -2 Q V^T + 1/196 ; X0 = 2I - M   (98-tile exact-fit GEMMs)
    dim3 g98(2,2,NB);
    k_bgemm98<<<g98,196>>>(pV, pV, pM, DM, 1,  2.f, 0.f, 1.f);
    k_bgemm98<<<g98,196>>>(pQ, pV, pP, DM, 1, -2.f, 1.f/(float)NT, 0.f);
    k_x0<<<(NB*NT*NT + 255)/256, 256>>>(pM, pXa);
    // 4. Newton-Schulz x3: T = 2I - M@X ; X' = X@T
    float* Xc = pXa; float* Xn = pXb;
    for (int i=0;i<3;i++){
        k_bgemm98<<<g98,196>>>(pM, Xc, pT, NT, 0, -1.f, 0.f, 2.f);
        k_bgemm98<<<g98,196>>>(Xc, pT, Xn, NT, 0,  1.f, 0.f, 0.f);
        float* t = Xc; Xc = Xn; Xn = t;
    }
    // 5. ADMM (fused, 50 iters) -> normalized coeffs
    k_admm<<<dim3(4,NB), 343, admm_smem>>>(Xc, pP, pCf);
    // 6. out = coeffs @ V
    k_bgemm<<<dim3(4,2,NB),256>>>(pCf, pV, pO, NT, DM, NT, 0, 1.f, 0.f, 0.f);
    // 7. pool + head
    k_pool<<<NB, 256>>>(pO, pPool);
    k_head<<<NB, 256>>>(pPool, mlg, mlb, mlw, mlwb, out);
}

// round 9
// speedup vs baseline: 2.0498x; 1.3390x over previous
#include <cuda_runtime.h>
#include <cuda_bf16.h>
#include <stdint.h>

#define NB 32
#define NT 196
#define PD 768
#define DM 512
#define NC 1000
#define MTOT (NB*NT)

__device__ float g_X [(size_t)MTOT*PD];
__device__ float g_Q [(size_t)MTOT*DM];
__device__ float g_V [(size_t)MTOT*DM];
__device__ float g_M [(size_t)NB*NT*NT];
__device__ float g_Xa[(size_t)NB*NT*NT];
__device__ float g_Xb[(size_t)NB*NT*NT];
__device__ float g_T [(size_t)NB*NT*NT];
__device__ float g_P [(size_t)NB*NT*NT];
__device__ float g_Cf[(size_t)NB*NT*NT];
__device__ float g_O [(size_t)MTOT*DM];
__device__ float g_pool[NB*DM];

__device__ __forceinline__ float clipf(float x){ return fminf(fmaxf(x, 0.f), 1.f); }

__device__ __forceinline__ float4 ld4g(const float* p, int rem){
    if (rem >= 4) return *(const float4*)p;
    float4 v = make_float4(0.f,0.f,0.f,0.f);
    if (rem > 0) v.x = p[0];
    if (rem > 1) v.y = p[1];
    if (rem > 2) v.z = p[2];
    return v;
}

__device__ __forceinline__ void mma16816(float* d,
        uint32_t a0, uint32_t a1, uint32_t a2, uint32_t a3,
        uint32_t b0, uint32_t b1){
    asm volatile(
        "mma.sync.aligned.m16n8k16.row.col.f32.bf16.bf16.f32 "
        "{%0,%1,%2,%3},{%4,%5,%6,%7},{%8,%9},{%0,%1,%2,%3};"
        : "+f"(d[0]), "+f"(d[1]), "+f"(d[2]), "+f"(d[3])
        : "r"(a0), "r"(a1), "r"(a2), "r"(a3), "r"(b0), "r"(b1));
}

// ---------------- patchify + LN(768) + pos ----------------
__global__ void k_patchify(const float* __restrict__ img, const float* __restrict__ g,
                           const float* __restrict__ bb, const float* __restrict__ pos){
    int bn = blockIdx.x, b = bn / NT, n = bn % NT;
    int hh = n / 14, ww = n % 14;
    int tid = threadIdx.x, ph = tid >> 4, pw = tid & 15;
    const float* ib = img + (size_t)b*3*224*224 + (size_t)(hh*16+ph)*224 + (ww*16+pw);
    float v0 = ib[0], v1 = ib[224*224], v2 = ib[2*224*224];
    __shared__ float red[256]; __shared__ float smu, srs;
    red[tid] = v0+v1+v2; __syncthreads();
    for (int o=128;o;o>>=1){ if (tid<o) red[tid]+=red[tid+o]; __syncthreads(); }
    if (!tid) smu = red[0]/768.f;
    __syncthreads();
    float mu = smu, d0=v0-mu, d1=v1-mu, d2=v2-mu;
    red[tid] = d0*d0+d1*d1+d2*d2; __syncthreads();
    for (int o=128;o;o>>=1){ if (tid<o) red[tid]+=red[tid+o]; __syncthreads(); }
    if (!tid) srs = rsqrtf(red[0]/768.f + 1e-5f);
    __syncthreads();
    float rs = srs;
    float* xo = g_X + (size_t)bn*PD;
    const float* pp = pos + (size_t)n*PD;
    int q = tid;     xo[q] = d0*rs*g[q] + bb[q] + pp[q];
    q = 256+tid;     xo[q] = d1*rs*g[q] + bb[q] + pp[q];
    q = 512+tid;     xo[q] = d2*rs*g[q] + bb[q] + pp[q];
}

// ---------------- fused projections: z=0 -> Q, z=1 -> V. 128x128, double-buffered ----------------
__global__ void __launch_bounds__(256,2) k_proj(const float* __restrict__ X,
                       const float* __restrict__ Wq, const float* __restrict__ bq,
                       const float* __restrict__ Wv, const float* __restrict__ bv,
                       float* __restrict__ Qo, float* __restrict__ Vo){
    __shared__ float As[2][16][128];
    __shared__ float Bs[2][16][128];
    const float* B   = blockIdx.z ? Wv : Wq;
    const float* bia = blockIdx.z ? bv : bq;
    float* C         = blockIdx.z ? Vo : Qo;
    const int Nv = DM, Kv = PD;
    int tid = threadIdx.x;
    int m0 = blockIdx.y<<7, n0 = blockIdx.x<<7;
    int ty = tid>>4, tx = tid&15;
    int aRow = tid>>1, aK = (tid&1)<<3;
    int bK = tid>>4, bN = (tid&15)<<3;
    const float* Ap = X + (size_t)(m0+aRow)*Kv + aK;
    const float* Bp = B + (size_t)bK*Nv + n0 + bN;
    float4 pa0 = *(const float4*)(Ap);
    float4 pa1 = *(const float4*)(Ap+4);
    float4 pb0 = *(const float4*)(Bp);
    float4 pb1 = *(const float4*)(Bp+4);
    As[0][aK+0][aRow]=pa0.x; As[0][aK+1][aRow]=pa0.y; As[0][aK+2][aRow]=pa0.z; As[0][aK+3][aRow]=pa0.w;
    As[0][aK+4][aRow]=pa1.x; As[0][aK+5][aRow]=pa1.y; As[0][aK+6][aRow]=pa1.z; As[0][aK+7][aRow]=pa1.w;
    *(float4*)&Bs[0][bK][bN] = pb0; *(float4*)&Bs[0][bK][bN+4] = pb1;
    __syncthreads();
    float acc[8][8] = {};
    const int NP = Kv>>4;
    int buf = 0;
    for (int p=0;p<NP;p++){
        bool more = (p+1)<NP;
        if (more){
            int k0 = (p+1)<<4;
            pa0 = *(const float4*)(Ap + k0);
            pa1 = *(const float4*)(Ap + k0 + 4);
            pb0 = *(const float4*)(Bp + (size_t)k0*Nv);
            pb1 = *(const float4*)(Bp + (size_t)k0*Nv + 4);
        }
#pragma unroll
        for (int kk=0;kk<16;kk++){
            float4 a0=*(const float4*)&As[buf][kk][ty<<3];
            float4 a1=*(const float4*)&As[buf][kk][(ty<<3)+4];
            float4 b0=*(const float4*)&Bs[buf][kk][tx<<3];
            float4 b1=*(const float4*)&Bs[buf][kk][(tx<<3)+4];
            float av[8]={a0.x,a0.y,a0.z,a0.w,a1.x,a1.y,a1.z,a1.w};
            float bw[8]={b0.x,b0.y,b0.z,b0.w,b1.x,b1.y,b1.z,b1.w};
#pragma unroll
            for (int r=0;r<8;r++)
#pragma unroll
                for (int c=0;c<8;c++)
                    acc[r][c] = fmaf(av[r], bw[c], acc[r][c]);
        }
        if (more){
            int nb = buf^1;
            As[nb][aK+0][aRow]=pa0.x; As[nb][aK+1][aRow]=pa0.y; As[nb][aK+2][aRow]=pa0.z; As[nb][aK+3][aRow]=pa0.w;
            As[nb][aK+4][aRow]=pa1.x; As[nb][aK+5][aRow]=pa1.y; As[nb][aK+6][aRow]=pa1.z; As[nb][aK+7][aRow]=pa1.w;
            *(float4*)&Bs[nb][bK][bN] = pb0; *(float4*)&Bs[nb][bK][bN+4] = pb1;
            __syncthreads();
            buf = nb;
        }
    }
    float4 bi0 = *(const float4*)(bia + n0 + (tx<<3));
    float4 bi1 = *(const float4*)(bia + n0 + (tx<<3) + 4);
#pragma unroll
    for (int r=0;r<8;r++){
        int gm = m0 + (ty<<3) + r;
        float4 o0 = make_float4(acc[r][0]+bi0.x, acc[r][1]+bi0.y, acc[r][2]+bi0.z, acc[r][3]+bi0.w);
        float4 o1 = make_float4(acc[r][4]+bi1.x, acc[r][5]+bi1.y, acc[r][6]+bi1.z, acc[r][7]+bi1.w);
        *(float4*)(C + (size_t)gm*Nv + n0 + (tx<<3)) = o0;
        *(float4*)(C + (size_t)gm*Nv + n0 + (tx<<3) + 4) = o1;
    }
}

// ---------------- in-place rowwise LN(512), then *scale ----------------
__global__ void k_ln512(float* __restrict__ y0, const float* __restrict__ g,
                        const float* __restrict__ bb, float scale){
    float* y = y0 + (size_t)blockIdx.x*DM;
    int tid = threadIdx.x;
    float v0 = y[tid], v1 = y[tid+256];
    __shared__ float red[256]; __shared__ float smu, srs;
    red[tid] = v0+v1; __syncthreads();
    for (int o=128;o;o>>=1){ if (tid<o) red[tid]+=red[tid+o]; __syncthreads(); }
    if (!tid) smu = red[0]/512.f;
    __syncthreads();
    float mu = smu, d0=v0-mu, d1=v1-mu;
    red[tid] = d0*d0+d1*d1; __syncthreads();
    for (int o=128;o;o>>=1){ if (tid<o) red[tid]+=red[tid+o]; __syncthreads(); }
    if (!tid) srs = rsqrtf(red[0]/512.f + 1e-5f);
    __syncthreads();
    float rs = srs;
    y[tid]     = (d0*rs*g[tid]     + bb[tid])     * scale;
    y[tid+256] = (d1*rs*g[tid+256] + bb[tid+256]) * scale;
}

// ---------------- batched GEMM, 98x98 tiles (exact fit for 196), 196 thr, 7x7 micro ----------------
__global__ void __launch_bounds__(196,2) k_bgemm98(const float* __restrict__ A0,
                        const float* __restrict__ B0, float* __restrict__ C0,
                        int K, int transB, float alpha, float c0, float diag){
    __shared__ float As[2][16][100];
    __shared__ float Bs[2][16][100];
    const float* A = A0 + (size_t)blockIdx.z*NT*K;
    const float* B = B0 + (size_t)blockIdx.z*NT*K;
    float* C = C0 + (size_t)blockIdx.z*NT*NT;
    int tid = threadIdx.x;
    int m0 = blockIdx.y*98, n0 = blockIdx.x*98;
    int ty = tid/14, tx = tid - ty*14;
    int lr = tid>>1, lk = (tid&1)<<3;
    const int NP = (K+15)>>4;
    float a_pf[8], b_pf[8];
    {
        const float* Ap = A + (size_t)(m0+lr)*K + lk;
#pragma unroll
        for (int j=0;j<8;j++) a_pf[j] = (lk+j < K) ? Ap[j] : 0.f;
        if (transB){
            const float* Bp = B + (size_t)(n0+lr)*K + lk;
#pragma unroll
            for (int j=0;j<8;j++) b_pf[j] = (lk+j < K) ? Bp[j] : 0.f;
        } else {
#pragma unroll
            for (int e=0;e<8;e++){
                int idx = tid + 196*e, kk = idx/98, n = idx - kk*98;
                b_pf[e] = (kk < K) ? B[(size_t)kk*NT + n0 + n] : 0.f;
            }
        }
    }
#pragma unroll
    for (int j=0;j<8;j++) As[0][lk+j][lr] = a_pf[j];
    if (transB){
#pragma unroll
        for (int j=0;j<8;j++) Bs[0][lk+j][lr] = b_pf[j];
    } else {
#pragma unroll
        for (int e=0;e<8;e++){
            int idx = tid + 196*e, kk = idx/98, n = idx - kk*98;
            Bs[0][kk][n] = b_pf[e];
        }
    }
    __syncthreads();
    float acc[7][7] = {};
    int buf = 0;
    for (int p=0;p<NP;p++){
        bool more = (p+1)<NP;
        if (more){
            int k0 = (p+1)<<4;
            const float* Ap = A + (size_t)(m0+lr)*K + k0 + lk;
#pragma unroll
            for (int j=0;j<8;j++) a_pf[j] = (k0+lk+j < K) ? Ap[j] : 0.f;
            if (transB){
                const float* Bp = B + (size_t)(n0+lr)*K + k0 + lk;
#pragma unroll
                for (int j=0;j<8;j++) b_pf[j] = (k0+lk+j < K) ? Bp[j] : 0.f;
            } else {
#pragma unroll
                for (int e=0;e<8;e++){
                    int idx = tid + 196*e, kk = idx/98, n = idx - kk*98;
                    b_pf[e] = (k0+kk < K) ? B[(size_t)(k0+kk)*NT + n0 + n] : 0.f;
                }
            }
        }
#pragma unroll
        for (int kk=0;kk<16;kk++){
            float a[7], b[7];
#pragma unroll
            for (int r=0;r<7;r++) a[r] = As[buf][kk][ty*7+r];
#pragma unroll
            for (int c=0;c<7;c++) b[c] = Bs[buf][kk][tx*7+c];
#pragma unroll
            for (int r=0;r<7;r++)
#pragma unroll
                for (int c=0;c<7;c++)
                    acc[r][c] = fmaf(a[r], b[c], acc[r][c]);
        }
        if (more){
            int nb = buf^1;
#pragma unroll
            for (int j=0;j<8;j++) As[nb][lk+j][lr] = a_pf[j];
            if (transB){
#pragma unroll
                for (int j=0;j<8;j++) Bs[nb][lk+j][lr] = b_pf[j];
            } else {
#pragma unroll
                for (int e=0;e<8;e++){
                    int idx = tid + 196*e, kk = idx/98, n = idx - kk*98;
                    Bs[nb][kk][n] = b_pf[e];
                }
            }
            __syncthreads();
            buf = nb;
        }
    }
#pragma unroll
    for (int r=0;r<7;r++){
        int gm = m0 + ty*7 + r;
#pragma unroll
        for (int c=0;c<7;c++){
            int gn = n0 + tx*7 + c;
            C[(size_t)gm*NT+gn] = fmaf(alpha, acc[r][c], c0) + ((gm==gn)?diag:0.f);
        }
    }
}

// ---------------- batched GEMM 128x128 (used for out = Cf@V) ----------------
__global__ void __launch_bounds__(256,2) k_bgemm(const float* __restrict__ A0, const float* __restrict__ B0,
                        float* __restrict__ C0, int M, int N, int K, int transB,
                        float alpha, float c0, float diag){
    __shared__ float As[2][16][128];
    __shared__ float Bs[2][16][128];
    const float* A = A0 + (size_t)blockIdx.z*M*K;
    const float* B = B0 + (size_t)blockIdx.z*((size_t)N*K);
    float* C = C0 + (size_t)blockIdx.z*M*N;
    int tid = threadIdx.x;
    int m0 = blockIdx.y<<7, n0 = blockIdx.x<<7;
    int ty = tid>>4, tx = tid&15;
    int aRow = tid>>1, aK = (tid&1)<<3;
    bool aok = (m0+aRow) < M;
    int bRT = tid>>1, bKT = (tid&1)<<3;
    bool bokT = (n0+bRT) < N;
    int bK = tid>>4, bN = (tid&15)<<3;
    const int NP = (K+15)>>4;
    float4 pa0,pa1,pb0,pb1;
    {
        const float* Ap = A + (size_t)(m0+aRow)*K + aK;
        int remA = aok ? (K - aK) : 0;
        pa0 = ld4g(Ap, remA); pa1 = ld4g(Ap+4, remA-4);
        if (transB){
            const float* Bp = B + (size_t)(n0+bRT)*K + bKT;
            int remB = bokT ? (K - bKT) : 0;
            pb0 = ld4g(Bp, remB); pb1 = ld4g(Bp+4, remB-4);
        } else {
            const float* Bp = B + (size_t)bK*N + n0 + bN;
            int remB = (bK < K) ? (N-(n0+bN)) : 0;
            pb0 = ld4g(Bp, remB); pb1 = ld4g(Bp+4, remB-4);
        }
    }
    As[0][aK+0][aRow]=pa0.x; As[0][aK+1][aRow]=pa0.y; As[0][aK+2][aRow]=pa0.z; As[0][aK+3][aRow]=pa0.w;
    As[0][aK+4][aRow]=pa1.x; As[0][aK+5][aRow]=pa1.y; As[0][aK+6][aRow]=pa1.z; As[0][aK+7][aRow]=pa1.w;
    if (transB){
        Bs[0][bKT+0][bRT]=pb0.x; Bs[0][bKT+1][bRT]=pb0.y; Bs[0][bKT+2][bRT]=pb0.z; Bs[0][bKT+3][bRT]=pb0.w;
        Bs[0][bKT+4][bRT]=pb1.x; Bs[0][bKT+5][bRT]=pb1.y; Bs[0][bKT+6][bRT]=pb1.z; Bs[0][bKT+7][bRT]=pb1.w;
    } else {
        *(float4*)&Bs[0][bK][bN] = pb0; *(float4*)&Bs[0][bK][bN+4] = pb1;
    }
    __syncthreads();
    float acc[8][8] = {};
    int buf = 0;
    for (int p=0;p<NP;p++){
        bool more = (p+1)<NP;
        if (more){
            int k0 = (p+1)<<4;
            const float* Ap = A + (size_t)(m0+aRow)*K + k0 + aK;
            int remA = aok ? (K - (k0+aK)) : 0;
            pa0 = ld4g(Ap, remA); pa1 = ld4g(Ap+4, remA-4);
            if (transB){
                const float* Bp = B + (size_t)(n0+bRT)*K + k0 + bKT;
                int remB = bokT ? (K - (k0+bKT)) : 0;
                pb0 = ld4g(Bp, remB); pb1 = ld4g(Bp+4, remB-4);
            } else {
                const float* Bp = B + (size_t)(k0+bK)*N + n0 + bN;
                int remB = ((k0+bK) < K) ? (N-(n0+bN)) : 0;
                pb0 = ld4g(Bp, remB); pb1 = ld4g(Bp+4, remB-4);
            }
        }
#pragma unroll
        for (int kk=0;kk<16;kk++){
            float4 a0=*(const float4*)&As[buf][kk][ty<<3];
            float4 a1=*(const float4*)&As[buf][kk][(ty<<3)+4];
            float4 b0=*(const float4*)&Bs[buf][kk][tx<<3];
            float4 b1=*(const float4*)&Bs[buf][kk][(tx<<3)+4];
            float av[8]={a0.x,a0.y,a0.z,a0.w,a1.x,a1.y,a1.z,a1.w};
            float bw[8]={b0.x,b0.y,b0.z,b0.w,b1.x,b1.y,b1.z,b1.w};
#pragma unroll
            for (int r=0;r<8;r++)
#pragma unroll
                for (int c=0;c<8;c++)
                    acc[r][c] = fmaf(av[r], bw[c], acc[r][c]);
        }
        if (more){
            int nb = buf^1;
            As[nb][aK+0][aRow]=pa0.x; As[nb][aK+1][aRow]=pa0.y; As[nb][aK+2][aRow]=pa0.z; As[nb][aK+3][aRow]=pa0.w;
            As[nb][aK+4][aRow]=pa1.x; As[nb][aK+5][aRow]=pa1.y; As[nb][aK+6][aRow]=pa1.z; As[nb][aK+7][aRow]=pa1.w;
            if (transB){
                Bs[nb][bKT+0][bRT]=pb0.x; Bs[nb][bKT+1][bRT]=pb0.y; Bs[nb][bKT+2][bRT]=pb0.z; Bs[nb][bKT+3][bRT]=pb0.w;
                Bs[nb][bKT+4][bRT]=pb1.x; Bs[nb][bKT+5][bRT]=pb1.y; Bs[nb][bKT+6][bRT]=pb1.z; Bs[nb][bKT+7][bRT]=pb1.w;
            } else {
                *(float4*)&Bs[nb][bK][bN] = pb0; *(float4*)&Bs[nb][bK][bN+4] = pb1;
            }
            __syncthreads();
            buf = nb;
        }
    }
#pragma unroll
    for (int r=0;r<8;r++){
        int gm = m0 + (ty<<3) + r;
        if (gm >= M) continue;
#pragma unroll
        for (int c=0;c<8;c++){
            int gn = n0 + (tx<<3) + c;
            if (gn >= N) continue;
            C[(size_t)gm*N+gn] = fmaf(alpha, acc[r][c], c0) + ((gm==gn)?diag:0.f);
        }
    }
}

// ---------------- X0 = 2I - M (elementwise) ----------------
__global__ void k_x0(const float* __restrict__ Mm, float* __restrict__ X){
    size_t idx = (size_t)blockIdx.x*256 + threadIdx.x;
    if (idx >= (size_t)NB*NT*NT) return;
    int w = (int)(idx % (NT*NT));
    int i = w / NT, j = w - i*NT;
    X[idx] = ((i==j)?2.f:0.f) - Mm[idx];
}

// ---------------- ADMM on tensor cores: mma.sync bf16 3-pass split ----------------
// Per CTA (tb,b): 49 tokens (padded M=64), i-dim N=200 (196+4 pad), k-dim 208.
// smem (bf16, word-stride 108): MH/ML = Minv hi/lo [200][216], RH/RL = rhs hi/lo [64][216].
// 512 thr = 16 warps: mw=warp>>2 m-tile, nq=warp&3 n-quarter (tiles {7,6,6,6}).
#define ADMM_SMEM 228096
__global__ void __launch_bounds__(512,1) k_admm_mma(const float* __restrict__ Minv,
        const float* __restrict__ P, float* __restrict__ Cf){
    extern __shared__ __align__(16) unsigned char smraw[];
    uint16_t* MH = (uint16_t*)smraw;          // 200*216
    uint16_t* ML = MH + 200*216;
    uint16_t* RH = ML + 200*216;              // 64*216
    uint16_t* RL = RH + 64*216;
    uint32_t* MH32 = (uint32_t*)MH;
    uint32_t* ML32 = (uint32_t*)ML;
    uint32_t* RH32 = (uint32_t*)RH;
    uint32_t* RL32 = (uint32_t*)RL;
    int b = blockIdx.y, tb = blockIdx.x;
    int tid = threadIdx.x, lane = tid&31, warp = tid>>5;
    int mw = warp>>2, nq = warp&3;
    int nb0 = (nq==0)?0:(nq==1)?7:(nq==2)?13:19;
    int cnt = (nq==0)?7:6;
    int q = lane&3, lr = lane>>2;
    int row0 = mw*16 + lr;                 // 0..63 (token-row within CTA block; +8 for upper half)
    int tok0 = tb*49;
    // zero all smem (pads must be 0)
    { uint32_t* w = (uint32_t*)smraw;
      for (int i=tid; i<ADMM_SMEM/4; i+=512) w[i] = 0u; }
    __syncthreads();
    // convert Minv -> bf16 hi/lo in smem
    const float* Mb = Minv + (size_t)b*NT*NT;
    for (int idx=tid; idx<NT*NT; idx+=512){
        int i = idx/NT, j = idx-i*NT;
        float v = Mb[idx];
        __nv_bfloat16 h = __float2bfloat16_rn(v);
        float lo = v - __bfloat162float(h);
        __nv_bfloat16 l = __float2bfloat16_rn(lo);
        MH[i*216+j] = *(uint16_t*)&h;
        ML[i*216+j] = *(uint16_t*)&l;
    }
    // load p fragments (D-layout: d0,d1 = (row0, i0),(row0,i0+1); d2,d3 = row0+8)
    float p[7][4], s[7][4], D[7][4];
#pragma unroll
    for (int t=0;t<7;t++)
#pragma unroll
        for (int e=0;e<4;e++){ p[t][e]=0.f; s[t][e]=0.f; }
#pragma unroll
    for (int t=0;t<7;t++){
        if (t < cnt){
            int i0 = (nb0+t)*8 + 2*q;
            if (i0+1 < NT){
                if (row0 < 49){
                    float2 v = *(const float2*)(P + ((size_t)b*NT + tok0 + row0)*NT + i0);
                    p[t][0]=v.x; p[t][1]=v.y;
                }
                if (row0+8 < 49){
                    float2 v = *(const float2*)(P + ((size_t)b*NT + tok0 + row0+8)*NT + i0);
                    p[t][2]=v.x; p[t][3]=v.y;
                }
            }
        }
    }
    __syncthreads();
    for (int it=0; it<50; it++){
        // rhs = 2clip(s)-s-p -> RH/RL  (s=0 initially -> -p, exact)
#pragma unroll
        for (int t=0;t<7;t++){
            if (t < cnt){
                int colw = (nb0+t)*4 + q;
                float r0 = 2.f*clipf(s[t][0]) - s[t][0] - p[t][0];
                float r1 = 2.f*clipf(s[t][1]) - s[t][1] - p[t][1];
                float r2 = 2.f*clipf(s[t][2]) - s[t][2] - p[t][2];
                float r3 = 2.f*clipf(s[t][3]) - s[t][3] - p[t][3];
                __nv_bfloat162 h01 = __floats2bfloat162_rn(r0, r1);
                __nv_bfloat162 h23 = __floats2bfloat162_rn(r2, r3);
                float l0 = r0 - __bfloat162float(h01.x);
                float l1 = r1 - __bfloat162float(h01.y);
                float l2 = r2 - __bfloat162float(h23.x);
                float l3 = r3 - __bfloat162float(h23.y);
                __nv_bfloat162 g01 = __floats2bfloat162_rn(l0, l1);
                __nv_bfloat162 g23 = __floats2bfloat162_rn(l2, l3);
                RH32[row0*108 + colw]     = *(uint32_t*)&h01;
                RH32[(row0+8)*108 + colw] = *(uint32_t*)&h23;
                RL32[row0*108 + colw]     = *(uint32_t*)&g01;
                RL32[(row0+8)*108 + colw] = *(uint32_t*)&g23;
            }
        }
        __syncthreads();
        // matvec D = rhs @ Minv (B[k][n] = Minv[n][k] via symmetry)
#pragma unroll
        for (int t=0;t<7;t++)
#pragma unroll
            for (int e=0;e<4;e++) D[t][e] = 0.f;
        for (int ks=0; ks<13; ks++){
            int kw = ks*8 + q;
            int aw = row0*108 + kw;
            uint32_t ah0 = RH32[aw],     ah1 = RH32[aw+864], ah2 = RH32[aw+4], ah3 = RH32[aw+868];
            uint32_t al0 = RL32[aw],     al1 = RL32[aw+864], al2 = RL32[aw+4], al3 = RL32[aw+868];
#pragma unroll
            for (int t=0;t<7;t++){
                if (t < cnt){
                    int bw = ((nb0+t)*8 + lr)*108 + kw;
                    uint32_t bh0 = MH32[bw], bh1 = MH32[bw+4];
                    uint32_t bl0 = ML32[bw], bl1 = ML32[bw+4];
                    mma16816(D[t], ah0,ah1,ah2,ah3, bh0,bh1);
                    mma16816(D[t], ah0,ah1,ah2,ah3, bl0,bl1);
                    mma16816(D[t], al0,al1,al2,al3, bh0,bh1);
                }
            }
        }
        // s <- D + s - clip(s)   (s=0 first iter -> s=D, exact)
#pragma unroll
        for (int t=0;t<7;t++){
            if (t < cnt){
#pragma unroll
                for (int e=0;e<4;e++)
                    s[t][e] = D[t][e] + s[t][e] - clipf(s[t][e]);
            }
        }
        __syncthreads();
    }
    // z = clip(s); rowwise sums -> normalize -> write Cf
    float rs0 = 0.f, rs1 = 0.f;
#pragma unroll
    for (int t=0;t<7;t++){
        if (t < cnt){
            rs0 += clipf(s[t][0]) + clipf(s[t][1]);
            rs1 += clipf(s[t][2]) + clipf(s[t][3]);
        }
    }
    rs0 += __shfl_xor_sync(0xffffffffu, rs0, 1);
    rs0 += __shfl_xor_sync(0xffffffffu, rs0, 2);
    rs1 += __shfl_xor_sync(0xffffffffu, rs1, 1);
    rs1 += __shfl_xor_sync(0xffffffffu, rs1, 2);
    float* sc = (float*)MH;   // Minv dead; 64x4 scratch
    if (q == 0){
        sc[row0*4 + nq] = rs0;
        sc[(row0+8)*4 + nq] = rs1;
    }
    __syncthreads();
    float inv0 = 1.f/(sc[row0*4]+sc[row0*4+1]+sc[row0*4+2]+sc[row0*4+3] + 1e-10f);
    float inv1 = 1.f/(sc[(row0+8)*4]+sc[(row0+8)*4+1]+sc[(row0+8)*4+2]+sc[(row0+8)*4+3] + 1e-10f);
#pragma unroll
    for (int t=0;t<7;t++){
        if (t < cnt){
            int i0 = (nb0+t)*8 + 2*q;
            if (i0+1 < NT){
                if (row0 < 49){
                    float2 o; o.x = clipf(s[t][0])*inv0; o.y = clipf(s[t][1])*inv0;
                    *(float2*)(Cf + ((size_t)b*NT + tok0 + row0)*NT + i0) = o;
                }
                if (row0+8 < 49){
                    float2 o; o.x = clipf(s[t][2])*inv1; o.y = clipf(s[t][3])*inv1;
                    *(float2*)(Cf + ((size_t)b*NT + tok0 + row0+8)*NT + i0) = o;
                }
            }
        }
    }
}

// ---------------- pool: mean over tokens ----------------
__global__ void k_pool(const float* __restrict__ O, float* __restrict__ pooled){
    int b = blockIdx.x, tid = threadIdx.x;
    const float* Ob = O + (size_t)b*NT*DM;
    float s0=0.f, s1=0.f;
    for (int n=0;n<NT;n++){ s0 += Ob[(size_t)n*DM+tid]; s1 += Ob[(size_t)n*DM+256+tid]; }
    pooled[b*DM+tid] = s0/(float)NT;
    pooled[b*DM+256+tid] = s1/(float)NT;
}

// ---------------- head: LN + GEMM(512x1000) + softmax ----------------
__global__ void k_head(const float* __restrict__ pooled, const float* __restrict__ g,
                       const float* __restrict__ bb, const float* __restrict__ W,
                       const float* __restrict__ wb, float* __restrict__ out){
    int b = blockIdx.x, tid = threadIdx.x;
    __shared__ float xs[512]; __shared__ float red[256]; __shared__ float smu, srs, sred;
    float v0 = pooled[b*DM+tid], v1 = pooled[b*DM+256+tid];
    red[tid] = v0+v1; __syncthreads();
    for (int o=128;o;o>>=1){ if (tid<o) red[tid]+=red[tid+o]; __syncthreads(); }
    if (!tid) smu = red[0]/512.f;
    __syncthreads();
    float mu = smu, d0=v0-mu, d1=v1-mu;
    red[tid] = d0*d0+d1*d1; __syncthreads();
    for (int o=128;o;o>>=1){ if (tid<o) red[tid]+=red[tid+o]; __syncthreads(); }
    if (!tid) srs = rsqrtf(red[0]/512.f + 1e-5f);
    __syncthreads();
    float rs = srs;
    xs[tid] = d0*rs*g[tid]+bb[tid];
    xs[tid+256] = d1*rs*g[tid+256]+bb[tid+256];
    __syncthreads();
    float lg[4];
#pragma unroll
    for (int c4=0;c4<4;c4++){
        int c = c4*256 + tid;
        float acc = 0.f;
        if (c < NC){
            for (int k=0;k<512;k++) acc = fmaf(xs[k], W[(size_t)k*NC+c], acc);
            acc += wb[c];
        } else acc = -1e30f;
        lg[c4] = acc;
    }
    float mx = fmaxf(fmaxf(lg[0],lg[1]),fmaxf(lg[2],lg[3]));
    red[tid] = mx; __syncthreads();
    for (int o=128;o;o>>=1){ if (tid<o) red[tid]=fmaxf(red[tid],red[tid+o]); __syncthreads(); }
    if (!tid) sred = red[0];
    __syncthreads();
    mx = sred;
    float es = 0.f;
#pragma unroll
    for (int c4=0;c4<4;c4++){ lg[c4] = __expf(lg[c4]-mx); if (c4*256+tid < NC) es += lg[c4]; }
    red[tid] = es; __syncthreads();
    for (int o=128;o;o>>=1){ if (tid<o) red[tid]+=red[tid+o]; __syncthreads(); }
    if (!tid) sred = red[0];
    __syncthreads();
    float inv = 1.f/sred;
#pragma unroll
    for (int c4=0;c4<4;c4++){ int c = c4*256+tid; if (c < NC) out[(size_t)b*NC+c] = lg[c4]*inv; }
}

extern "C" void kernel_launch(void* const* d_in, const int* in_sizes, int n_in,
                              void* d_out, int out_size){
    const float* img   = (const float*)d_in[0];
    const float* lpg   = (const float*)d_in[1];
    const float* lpb   = (const float*)d_in[2];
    const float* wq_w  = (const float*)d_in[3];
    const float* wq_b  = (const float*)d_in[4];
    const float* lnq_g = (const float*)d_in[5];
    const float* lnq_b = (const float*)d_in[6];
    const float* wv_w  = (const float*)d_in[7];
    const float* wv_b  = (const float*)d_in[8];
    const float* lnv_g = (const float*)d_in[9];
    const float* lnv_b = (const float*)d_in[10];
    const float* pos   = (const float*)d_in[11];
    const float* mlg   = (const float*)d_in[12];
    const float* mlb   = (const float*)d_in[13];
    const float* mlw   = (const float*)d_in[14];
    const float* mlwb  = (const float*)d_in[15];
    float* out = (float*)d_out;

    float *pX,*pQ,*pV,*pM,*pXa,*pXb,*pT,*pP,*pCf,*pO,*pPool;
    cudaGetSymbolAddress((void**)&pX, g_X);
    cudaGetSymbolAddress((void**)&pQ, g_Q);
    cudaGetSymbolAddress((void**)&pV, g_V);
    cudaGetSymbolAddress((void**)&pM, g_M);
    cudaGetSymbolAddress((void**)&pXa, g_Xa);
    cudaGetSymbolAddress((void**)&pXb, g_Xb);
    cudaGetSymbolAddress((void**)&pT, g_T);
    cudaGetSymbolAddress((void**)&pP, g_P);
    cudaGetSymbolAddress((void**)&pCf, g_Cf);
    cudaGetSymbolAddress((void**)&pO, g_O);
    cudaGetSymbolAddress((void**)&pPool, g_pool);

    static int s_attr_done = 0;
    if (!s_attr_done){
        cudaFuncSetAttribute(k_admm_mma, cudaFuncAttributeMaxDynamicSharedMemorySize, ADMM_SMEM);
        s_attr_done = 1;
    }

    // 1. patchify + LN + pos
    k_patchify<<<MTOT, 256>>>(img, lpg, lpb, pos);
    // 2. fused Q/V projections + LN (V scaled by 1/196)
    k_proj<<<dim3(DM/128, MTOT/128, 2), 256>>>(pX, wq_w, wq_b, wv_w, wv_b, pQ, pV);
    k_ln512<<<MTOT, 256>>>(pQ, lnq_g, lnq_b, 1.f);
    k_ln512<<<MTOT, 256>>>(pV, lnv_g, lnv_b, 1.f/(float)NT);
    // 3. M = I + 2VV^T ; p = -2 Q V^T + 1/196 ; X0 = 2I - M
    dim3 g98(2,2,NB);
    k_bgemm98<<<g98,196>>>(pV, pV, pM, DM, 1,  2.f, 0.f, 1.f);
    k_bgemm98<<<g98,196>>>(pQ, pV, pP, DM, 1, -2.f, 1.f/(float)NT, 0.f);
    k_x0<<<(NB*NT*NT + 255)/256, 256>>>(pM, pXa);
    // 4. Newton-Schulz x3: T = 2I - M@X ; X' = X@T
    float* Xc = pXa; float* Xn = pXb;
    for (int i=0;i<3;i++){
        k_bgemm98<<<g98,196>>>(pM, Xc, pT, NT, 0, -1.f, 0.f, 2.f);
        k_bgemm98<<<g98,196>>>(Xc, pT, Xn, NT, 0,  1.f, 0.f, 0.f);
        float* t = Xc; Xc = Xn; Xn = t;
    }
    // 5. ADMM on tensor cores (50 iters) -> normalized coeffs
    k_admm_mma<<<dim3(4,NB), 512, ADMM_SMEM>>>(Xc, pP, pCf);
    // 6. out = coeffs @ V
    k_bgemm<<<dim3(4,2,NB),256>>>(pCf, pV, pO, NT, DM, NT, 0, 1.f, 0.f, 0.f);
    // 7. pool + head
    k_pool<<<NB, 256>>>(pO, pPool);
    k_head<<<NB, 256>>>(pPool, mlg, mlb, mlw, mlwb, out);
}